// round 9
// baseline (speedup 1.0000x reference)
#include <cuda_runtime.h>
#include <cuda_fp16.h>

#define D 4096
#define NSTEPS 50
#define NCTA 294                 // 2 CTAs per SM (147 SMs' worth)
#define ROWS_PER_CTA 14
#define CACHED_ROWS 4            // rows per CTA held in SMEM (64 KB)
#define NTHREADS 1024

// Interleaved fp16 pairs: g_AB[r*2D + 2j] = M[r][j] = A+B, [..+1] = -B[r][j].
// Recurrence: theta_{t+1} = M theta_t + (-B) theta_{t-1}  (no delta needed).
__device__ __align__(16) __half g_AB[(size_t)2 * D * D];
__device__ unsigned int g_bar;      // arrival counter (monotonic per launch)
__device__ unsigned int g_release;  // step release word (single writer per step)

// ---------------------------------------------------------------------------
// prep: build interleaved (A+B, -B) fp16 pairs; reset barrier words.
// ---------------------------------------------------------------------------
__global__ void __launch_bounds__(256) prep_kernel(const float* __restrict__ A,
                                                   const float* __restrict__ B) {
    if (blockIdx.x == 0 && threadIdx.x == 0) { g_bar = 0; g_release = 0; }
    size_t i = (size_t)blockIdx.x * blockDim.x + threadIdx.x;  // float4 index
    float4 a = ((const float4*)A)[i];
    float4 b = ((const float4*)B)[i];
    uint4 o;
    __half2 p;
    p = __floats2half2_rn(a.x + b.x, -b.x); o.x = *(unsigned int*)&p;
    p = __floats2half2_rn(a.y + b.y, -b.y); o.y = *(unsigned int*)&p;
    p = __floats2half2_rn(a.z + b.z, -b.z); o.z = *(unsigned int*)&p;
    p = __floats2half2_rn(a.w + b.w, -b.w); o.w = *(unsigned int*)&p;
    ((uint4*)g_AB)[i] = o;
}

// acc += M[j]*cur + (-B)[j]*prev for 4 interleaved fp16 pairs in m
__device__ __forceinline__ float dotAB(uint4 m, float4 c, float4 p, float acc) {
    float2 f;
    f = __half22float2(*(__half2*)&m.x); acc = fmaf(f.x, c.x, acc); acc = fmaf(f.y, p.x, acc);
    f = __half22float2(*(__half2*)&m.y); acc = fmaf(f.x, c.y, acc); acc = fmaf(f.y, p.y, acc);
    f = __half22float2(*(__half2*)&m.z); acc = fmaf(f.x, c.z, acc); acc = fmaf(f.y, p.z, acc);
    f = __half22float2(*(__half2*)&m.w); acc = fmaf(f.x, c.w, acc); acc = fmaf(f.y, p.w, acc);
    return acc;
}

// ---------------------------------------------------------------------------
// Persistent recurrence kernel: 294 CTAs x 1024 threads, 2 CTAs/SM (occ 100%).
// 14 rows/CTA: warp (rg, ks) = 2-row group x 1024-elem K-segment (28 active
// warps, 4 idle).  Rows 0..3 cached in SMEM; rows 4..13 stream from L2.
// Vector SMEM double-buffer: theta_{t-1} stays on-chip; staging loads only
// the fresh theta_t.  Two-word global barrier.
// SMEM: v0 16K | v1 16K | part 256B | cached 64K = 98,560 B per CTA.
// ---------------------------------------------------------------------------
__global__ void __launch_bounds__(NTHREADS, 2) rnn_kernel(const float* __restrict__ init,
                                                          float* __restrict__ out) {
    extern __shared__ char smem[];
    float4* s_v0   = (float4*)smem;                    // vector buffer 0 (16 KB)
    float4* s_v1   = (float4*)(smem + 16384);          // vector buffer 1 (16 KB)
    float*  s_part = (float*)(smem + 32768);           // partials (256 B)
    uint4*  s_mat  = (uint4*)(smem + 33024);           // cached rows (64 KB)

    const int tid  = threadIdx.x;
    const int warp = tid >> 5;                         // 0..31
    const int lane = tid & 31;
    const int rg   = warp >> 2;                        // 0..7 (7 idle)
    const int ks   = warp & 3;                         // 0..3
    const int row_base = blockIdx.x * ROWS_PER_CTA;
    const int row0 = row_base + rg * 2;
    const bool active = (rg < 7);
    const bool cached = (rg < CACHED_ROWS / 2);        // rg 0..1 -> SMEM rows
    const int seg = ks * 256;                          // float4 offset of segment

    // Preload cached rows into SMEM (once).  Clamp OOB rows of tail CTAs.
#pragma unroll
    for (int it = 0; it < CACHED_ROWS; ++it) {
        int sr = min(row_base + it, D - 1);
        s_mat[it * 1024 + tid] = ((const uint4*)g_AB)[(size_t)sr * 1024 + tid];
    }

    // Streamed-row pointers (rg >= 2), clamped for tail CTAs
    const uint4* r0 = (const uint4*)g_AB + (size_t)min(row0 + 0, D - 1) * 1024;
    const uint4* r1 = (const uint4*)g_AB + (size_t)min(row0 + 1, D - 1) * 1024;
    // Cached-row pointers (rg < 2)
    const uint4* c0 = s_mat + (size_t)(rg * 2 + 0) * 1024;
    const uint4* c1 = s_mat + (size_t)(rg * 2 + 1) * 1024;

    // Prologue: buffer1 holds theta_{-1} = init_seq[0]
    s_v1[tid] = ((const float4*)init)[tid];
    __syncthreads();

    for (int t = 0; t < NSTEPS; ++t) {
        float4* s_cur  = (t & 1) ? s_v1 : s_v0;        // receives theta_t
        float4* s_prev = (t & 1) ? s_v0 : s_v1;        // holds theta_{t-1}

        // Stage fresh theta_t only (theta_{t-1} already on-chip)
        const float* th1 = (t == 0) ? init + D : out + (size_t)(t - 1) * D;
        s_cur[tid] = __ldcg((const float4*)th1 + tid);
        __syncthreads();

        if (active) {
            float a0 = 0.f, a1 = 0.f;
            if (cached) {
#pragma unroll 2
                for (int i = 0; i < 8; ++i) {
                    int idx = seg + i * 32 + lane;
                    float4 cv = s_cur[idx];
                    float4 pv = s_prev[idx];
                    a0 = dotAB(c0[idx], cv, pv, a0);
                    a1 = dotAB(c1[idx], cv, pv, a1);
                }
            } else {
#pragma unroll 2
                for (int i = 0; i < 8; ++i) {
                    int idx = seg + i * 32 + lane;
                    uint4 m0 = r0[idx];
                    uint4 m1 = r1[idx];
                    float4 cv = s_cur[idx];
                    float4 pv = s_prev[idx];
                    a0 = dotAB(m0, cv, pv, a0);
                    a1 = dotAB(m1, cv, pv, a1);
                }
            }
#pragma unroll
            for (int off = 16; off; off >>= 1) {
                a0 += __shfl_xor_sync(0xffffffffu, a0, off);
                a1 += __shfl_xor_sync(0xffffffffu, a1, off);
            }
            if (lane == 0) {
                s_part[(rg * 2 + 0) * 4 + ks] = a0;
                s_part[(rg * 2 + 1) * 4 + ks] = a1;
            }
        }
        __syncthreads();

        // Combine K-segment partials (deterministic order) and publish rows
        if (tid < ROWS_PER_CTA) {
            int row = row_base + tid;
            if (row < D) {
                float v = (s_part[tid * 4 + 0] + s_part[tid * 4 + 1]) +
                          (s_part[tid * 4 + 2] + s_part[tid * 4 + 3]);
                __stcg(out + (size_t)t * D + row, v);
            }
        }
        __syncthreads();

        // Device-wide step barrier: atomic arrivals + single-writer release
        if (tid == 0) {
            __threadfence();                           // release this CTA's rows
            unsigned int old = atomicAdd(&g_bar, 1u);
            unsigned int target = (unsigned int)(t + 1) * NCTA;
            if (old == target - 1u)
                *(volatile unsigned int*)&g_release = (unsigned int)(t + 1);
            while (*(volatile unsigned int*)&g_release < (unsigned int)(t + 1)) { }
            __threadfence();                           // acquire
        }
        __syncthreads();
    }
}

// ---------------------------------------------------------------------------
// Launch: prep (convert + barrier reset), then ONE persistent kernel.
// 98,560 B dynamic SMEM per CTA -> 2 CTAs co-resident per SM.
// ---------------------------------------------------------------------------
extern "C" void kernel_launch(void* const* d_in, const int* in_sizes, int n_in,
                              void* d_out, int out_size) {
    const float* init = (const float*)d_in[0];  // [2, D]
    const float* A    = (const float*)d_in[1];  // [D, D]
    const float* B    = (const float*)d_in[2];  // [D, D]
    float* out = (float*)d_out;                 // [NSTEPS, D]

    const int smem_bytes = 33024 + CACHED_ROWS * 1024 * 16;  // 98,560 B
    cudaFuncSetAttribute(rnn_kernel, cudaFuncAttributeMaxDynamicSharedMemorySize,
                         smem_bytes);

    prep_kernel<<<(D * (size_t)D / 4) / 256, 256>>>(A, B);
    rnn_kernel<<<NCTA, NTHREADS, smem_bytes>>>(init, out);
}

// round 11
// speedup vs baseline: 1.2644x; 1.2644x over previous
#include <cuda_runtime.h>
#include <cuda_fp16.h>

#define D 4096
#define NSTEPS 50
#define NCTA 147
#define ROWS_PER_CTA 28
#define CACHED_ROWS 12           // rows per CTA held in SMEM (192 KB)
#define NTHREADS 1024

// Interleaved fp16 pairs: g_AB[r*2D + 2j] = M[r][j] = A+B, [..+1] = -B[r][j].
// Recurrence: theta_{t+1} = M theta_t + (-B) theta_{t-1}.
__device__ __align__(16) __half g_AB[(size_t)2 * D * D];
__device__ unsigned int g_bar;      // arrival counter (monotonic per launch)
__device__ unsigned int g_release;  // step release word (single writer per step)

// ---------------------------------------------------------------------------
// prep: build interleaved (A+B, -B) fp16 pairs; reset barrier words.
// ---------------------------------------------------------------------------
__global__ void __launch_bounds__(256) prep_kernel(const float* __restrict__ A,
                                                   const float* __restrict__ B) {
    if (blockIdx.x == 0 && threadIdx.x == 0) { g_bar = 0; g_release = 0; }
    size_t i = (size_t)blockIdx.x * blockDim.x + threadIdx.x;  // float4 index
    float4 a = ((const float4*)A)[i];
    float4 b = ((const float4*)B)[i];
    uint4 o;
    __half2 p;
    p = __floats2half2_rn(a.x + b.x, -b.x); o.x = *(unsigned int*)&p;
    p = __floats2half2_rn(a.y + b.y, -b.y); o.y = *(unsigned int*)&p;
    p = __floats2half2_rn(a.z + b.z, -b.z); o.z = *(unsigned int*)&p;
    p = __floats2half2_rn(a.w + b.w, -b.w); o.w = *(unsigned int*)&p;
    ((uint4*)g_AB)[i] = o;
}

// acc += M[j]*cur + (-B)[j]*prev for 4 interleaved fp16 pairs in m
__device__ __forceinline__ float dotAB(uint4 m, float4 c, float4 p, float acc) {
    float2 f;
    f = __half22float2(*(__half2*)&m.x); acc = fmaf(f.x, c.x, acc); acc = fmaf(f.y, p.x, acc);
    f = __half22float2(*(__half2*)&m.y); acc = fmaf(f.x, c.y, acc); acc = fmaf(f.y, p.y, acc);
    f = __half22float2(*(__half2*)&m.z); acc = fmaf(f.x, c.z, acc); acc = fmaf(f.y, p.z, acc);
    f = __half22float2(*(__half2*)&m.w); acc = fmaf(f.x, c.w, acc); acc = fmaf(f.y, p.w, acc);
    return acc;
}

// ---------------------------------------------------------------------------
// Persistent recurrence kernel: 147 CTAs x 1024 threads (proven R5 config).
// Warp (rg, ks): 4-row group x 1024-elem K-segment.  Rows 0..11 cached in
// SMEM; rows 12..27 stream from L2.  Vector double-buffer: theta_{t-1} stays
// on-chip, staging loads only fresh theta_t (16 KB instead of 32 KB).
// Barrier: atomicAdd arrivals + single-writer release word (proven in R8).
// SMEM: v0 16K | v1 16K | part 512B | cached rows 192K = 224.5 KB.
// ---------------------------------------------------------------------------
__global__ void __launch_bounds__(NTHREADS, 1) rnn_kernel(const float* __restrict__ init,
                                                          float* __restrict__ out) {
    extern __shared__ char smem[];
    float4* s_v0   = (float4*)smem;                    // vector buffer 0 (16 KB)
    float4* s_v1   = (float4*)(smem + 16384);          // vector buffer 1 (16 KB)
    float*  s_part = (float*)(smem + 32768);           // partials (512 B)
    uint4*  s_mat  = (uint4*)(smem + 33280);           // cached rows (192 KB)

    const int tid  = threadIdx.x;
    const int warp = tid >> 5;
    const int lane = tid & 31;
    const int rg   = warp >> 2;                        // 0..7 (7 idle)
    const int ks   = warp & 3;                         // 0..3
    const int row_base = blockIdx.x * ROWS_PER_CTA;
    const int row0 = row_base + rg * 4;
    const bool rowOK  = (rg < 7) && (row0 < D);
    const bool cached = (rg < CACHED_ROWS / 4);        // rg 0..2 -> SMEM rows
    const int seg = ks * 256;                          // float4 offset of segment

    // Preload cached rows into SMEM (once).  Clamp OOB rows of the last CTA.
#pragma unroll
    for (int it = 0; it < CACHED_ROWS; ++it) {
        int sr = min(row_base + it, D - 1);
        s_mat[it * 1024 + tid] = ((const uint4*)g_AB)[(size_t)sr * 1024 + tid];
    }

    // Streamed-row pointers (rg >= 3), clamped for the partially-OOB last CTA
    const uint4* r0 = (const uint4*)g_AB + (size_t)min(row0 + 0, D - 1) * 1024;
    const uint4* r1 = (const uint4*)g_AB + (size_t)min(row0 + 1, D - 1) * 1024;
    const uint4* r2 = (const uint4*)g_AB + (size_t)min(row0 + 2, D - 1) * 1024;
    const uint4* r3 = (const uint4*)g_AB + (size_t)min(row0 + 3, D - 1) * 1024;
    // Cached-row pointers (rg < 3)
    const uint4* c0 = s_mat + (size_t)(rg * 4 + 0) * 1024;
    const uint4* c1 = s_mat + (size_t)(rg * 4 + 1) * 1024;
    const uint4* c2 = s_mat + (size_t)(rg * 4 + 2) * 1024;
    const uint4* c3 = s_mat + (size_t)(rg * 4 + 3) * 1024;

    // Prologue: buffer1 holds theta_{-1} = init_seq[0]
    s_v1[tid] = ((const float4*)init)[tid];
    __syncthreads();

    for (int t = 0; t < NSTEPS; ++t) {
        float4* s_cur  = (t & 1) ? s_v1 : s_v0;        // receives theta_t
        float4* s_prev = (t & 1) ? s_v0 : s_v1;        // holds theta_{t-1}

        // Stage fresh theta_t only (theta_{t-1} already on-chip)
        const float* th1 = (t == 0) ? init + D : out + (size_t)(t - 1) * D;
        s_cur[tid] = __ldcg((const float4*)th1 + tid);
        __syncthreads();

        if (rowOK) {
            float a0 = 0.f, a1 = 0.f, a2 = 0.f, a3 = 0.f;
            if (cached) {
#pragma unroll 2
                for (int i = 0; i < 8; ++i) {
                    int idx = seg + i * 32 + lane;
                    float4 cv = s_cur[idx];
                    float4 pv = s_prev[idx];
                    a0 = dotAB(c0[idx], cv, pv, a0);
                    a1 = dotAB(c1[idx], cv, pv, a1);
                    a2 = dotAB(c2[idx], cv, pv, a2);
                    a3 = dotAB(c3[idx], cv, pv, a3);
                }
            } else {
#pragma unroll 2
                for (int i = 0; i < 8; ++i) {
                    int idx = seg + i * 32 + lane;
                    uint4 m0 = r0[idx];
                    uint4 m1 = r1[idx];
                    uint4 m2 = r2[idx];
                    uint4 m3 = r3[idx];
                    float4 cv = s_cur[idx];
                    float4 pv = s_prev[idx];
                    a0 = dotAB(m0, cv, pv, a0);
                    a1 = dotAB(m1, cv, pv, a1);
                    a2 = dotAB(m2, cv, pv, a2);
                    a3 = dotAB(m3, cv, pv, a3);
                }
            }
#pragma unroll
            for (int off = 16; off; off >>= 1) {
                a0 += __shfl_xor_sync(0xffffffffu, a0, off);
                a1 += __shfl_xor_sync(0xffffffffu, a1, off);
                a2 += __shfl_xor_sync(0xffffffffu, a2, off);
                a3 += __shfl_xor_sync(0xffffffffu, a3, off);
            }
            if (lane == 0) {
                s_part[(rg * 4 + 0) * 4 + ks] = a0;
                s_part[(rg * 4 + 1) * 4 + ks] = a1;
                s_part[(rg * 4 + 2) * 4 + ks] = a2;
                s_part[(rg * 4 + 3) * 4 + ks] = a3;
            }
        }
        __syncthreads();                               // partials ready

        // Combine K-segment partials (deterministic order) and publish rows
        if (tid < ROWS_PER_CTA) {
            int row = row_base + tid;
            if (row < D) {
                float v = (s_part[tid * 4 + 0] + s_part[tid * 4 + 1]) +
                          (s_part[tid * 4 + 2] + s_part[tid * 4 + 3]);
                __stcg(out + (size_t)t * D + row, v);
            }
        }
        __syncthreads();

        // Device-wide step barrier: atomic arrivals + single-writer release
        // (proven R8 pattern; all 147 CTAs co-resident at 1 CTA/SM).
        if (tid == 0) {
            __threadfence();                           // release this CTA's rows
            unsigned int old = atomicAdd(&g_bar, 1u);
            unsigned int target = (unsigned int)(t + 1) * NCTA;
            if (old == target - 1u)
                *(volatile unsigned int*)&g_release = (unsigned int)(t + 1);
            while (*(volatile unsigned int*)&g_release < (unsigned int)(t + 1)) { }
            __threadfence();                           // acquire
        }
        __syncthreads();
    }
}

// ---------------------------------------------------------------------------
// Launch: prep (convert + barrier reset), then ONE persistent kernel with
// opt-in 224.5 KB dynamic SMEM (1 CTA/SM, 147 co-resident).
// ---------------------------------------------------------------------------
extern "C" void kernel_launch(void* const* d_in, const int* in_sizes, int n_in,
                              void* d_out, int out_size) {
    const float* init = (const float*)d_in[0];  // [2, D]
    const float* A    = (const float*)d_in[1];  // [D, D]
    const float* B    = (const float*)d_in[2];  // [D, D]
    float* out = (float*)d_out;                 // [NSTEPS, D]

    const int smem_bytes = 33280 + CACHED_ROWS * 1024 * 16;  // 229,888 B
    cudaFuncSetAttribute(rnn_kernel, cudaFuncAttributeMaxDynamicSharedMemorySize,
                         smem_bytes);

    prep_kernel<<<(D * (size_t)D / 4) / 256, 256>>>(A, B);
    rnn_kernel<<<NCTA, NTHREADS, smem_bytes>>>(init, out);
}

// round 12
// speedup vs baseline: 1.3312x; 1.0528x over previous
#include <cuda_runtime.h>
#include <cuda_fp16.h>

#define D 4096
#define NSTEPS 50
#define NCTA 256                 // 2 CTAs/SM on 128 SMs (all co-resident)
#define ROWS_PER_CTA 16
#define NTHREADS 512             // 16 warps: rg 0..3 x ks 0..3 — same warp shape as R5

// Interleaved fp16 pairs: g_AB[r*2D + 2j] = M[r][j] = A+B, [..+1] = -B[r][j].
// Recurrence: theta_{t+1} = M theta_t + (-B) theta_{t-1}.
__device__ __align__(16) __half g_AB[(size_t)2 * D * D];
__device__ unsigned int g_bar;   // arrival counter (monotonic per launch)

// ---------------------------------------------------------------------------
// prep: build interleaved (A+B, -B) fp16 pairs; reset barrier counter.
// ---------------------------------------------------------------------------
__global__ void __launch_bounds__(256) prep_kernel(const float* __restrict__ A,
                                                   const float* __restrict__ B) {
    if (blockIdx.x == 0 && threadIdx.x == 0) g_bar = 0;
    size_t i = (size_t)blockIdx.x * blockDim.x + threadIdx.x;  // float4 index
    float4 a = ((const float4*)A)[i];
    float4 b = ((const float4*)B)[i];
    uint4 o;
    __half2 p;
    p = __floats2half2_rn(a.x + b.x, -b.x); o.x = *(unsigned int*)&p;
    p = __floats2half2_rn(a.y + b.y, -b.y); o.y = *(unsigned int*)&p;
    p = __floats2half2_rn(a.z + b.z, -b.z); o.z = *(unsigned int*)&p;
    p = __floats2half2_rn(a.w + b.w, -b.w); o.w = *(unsigned int*)&p;
    ((uint4*)g_AB)[i] = o;
}

// acc += M[j]*cur + (-B)[j]*prev for 4 interleaved fp16 pairs in m
__device__ __forceinline__ float dotAB(uint4 m, float4 c, float4 p, float acc) {
    float2 f;
    f = __half22float2(*(__half2*)&m.x); acc = fmaf(f.x, c.x, acc); acc = fmaf(f.y, p.x, acc);
    f = __half22float2(*(__half2*)&m.y); acc = fmaf(f.x, c.y, acc); acc = fmaf(f.y, p.y, acc);
    f = __half22float2(*(__half2*)&m.z); acc = fmaf(f.x, c.z, acc); acc = fmaf(f.y, p.z, acc);
    f = __half22float2(*(__half2*)&m.w); acc = fmaf(f.x, c.w, acc); acc = fmaf(f.y, p.w, acc);
    return acc;
}

// ---------------------------------------------------------------------------
// Persistent recurrence kernel: 256 CTAs x 512 threads, 2 CTAs/SM (occ ~100%),
// per-warp work shape IDENTICAL to the best (R5) kernel: warp (rg, ks) owns a
// 4-row group x 1024-elem K-segment, 8 inner iterations.
// Rows rg==0 (4 rows, 64 KB) cached in SMEM; rg 1..3 stream from L2.
// Vector double-buffer with 2-step unrolled loop -> compile-time static SMEM
// addresses.  Barrier: R5-proven single-counter atomic spin.
// SMEM: v0 16K | v1 16K | part 256B | cached 64K = 98,560 B -> 2 CTAs/SM.
// ---------------------------------------------------------------------------
__global__ void __launch_bounds__(NTHREADS, 2) rnn_kernel(const float* __restrict__ init,
                                                          float* __restrict__ out) {
    extern __shared__ char smem[];
    float4* s_v0   = (float4*)smem;                    // vector buffer 0 (16 KB)
    float4* s_v1   = (float4*)(smem + 16384);          // vector buffer 1 (16 KB)
    float*  s_part = (float*)(smem + 32768);           // partials (256 B)
    uint4*  s_mat  = (uint4*)(smem + 33024);           // cached rows (64 KB)

    const int tid  = threadIdx.x;
    const int warp = tid >> 5;                         // 0..15
    const int lane = tid & 31;
    const int rg   = warp >> 2;                        // 0..3
    const int ks   = warp & 3;                         // 0..3
    const int row_base = blockIdx.x * ROWS_PER_CTA;
    const int row0 = row_base + rg * 4;                // always < D (exact tiling)
    const bool cached = (rg == 0);
    const int seg = ks * 256;                          // float4 offset of segment

    // Preload 4 cached rows (rows row_base..row_base+3) into SMEM once.
#pragma unroll
    for (int k = 0; k < 8; ++k)
        s_mat[tid + k * NTHREADS] =
            ((const uint4*)g_AB)[(size_t)row_base * 1024 + tid + k * NTHREADS];

    // Streamed-row pointers (rg >= 1); cached pointers (rg == 0)
    const uint4* r0 = (const uint4*)g_AB + (size_t)(row0 + 0) * 1024;
    const uint4* r1 = (const uint4*)g_AB + (size_t)(row0 + 1) * 1024;
    const uint4* r2 = (const uint4*)g_AB + (size_t)(row0 + 2) * 1024;
    const uint4* r3 = (const uint4*)g_AB + (size_t)(row0 + 3) * 1024;
    const uint4* c0 = s_mat + 0 * 1024;
    const uint4* c1 = s_mat + 1 * 1024;
    const uint4* c2 = s_mat + 2 * 1024;
    const uint4* c3 = s_mat + 3 * 1024;

    // Prologue: buffer1 holds theta_{-1} = init_seq[0]
    s_v1[tid]       = ((const float4*)init)[tid];
    s_v1[tid + 512] = ((const float4*)init)[tid + 512];
    __syncthreads();

    // One recurrence step with compile-time buffer roles.
#define RNN_STEP(T, SCUR, SPREV)                                               \
    {                                                                          \
        const float* th1 = ((T) == 0) ? init + D : out + (size_t)((T) - 1) * D;\
        (SCUR)[tid]       = __ldcg((const float4*)th1 + tid);                  \
        (SCUR)[tid + 512] = __ldcg((const float4*)th1 + tid + 512);            \
        __syncthreads();                                                       \
        float a0 = 0.f, a1 = 0.f, a2 = 0.f, a3 = 0.f;                          \
        if (cached) {                                                          \
            _Pragma("unroll 2")                                                \
            for (int i = 0; i < 8; ++i) {                                      \
                int idx = seg + i * 32 + lane;                                 \
                float4 cv = (SCUR)[idx];                                       \
                float4 pv = (SPREV)[idx];                                      \
                a0 = dotAB(c0[idx], cv, pv, a0);                               \
                a1 = dotAB(c1[idx], cv, pv, a1);                               \
                a2 = dotAB(c2[idx], cv, pv, a2);                               \
                a3 = dotAB(c3[idx], cv, pv, a3);                               \
            }                                                                  \
        } else {                                                               \
            _Pragma("unroll 2")                                                \
            for (int i = 0; i < 8; ++i) {                                      \
                int idx = seg + i * 32 + lane;                                 \
                uint4 m0 = r0[idx];                                            \
                uint4 m1 = r1[idx];                                            \
                uint4 m2 = r2[idx];                                            \
                uint4 m3 = r3[idx];                                            \
                float4 cv = (SCUR)[idx];                                       \
                float4 pv = (SPREV)[idx];                                      \
                a0 = dotAB(m0, cv, pv, a0);                                    \
                a1 = dotAB(m1, cv, pv, a1);                                    \
                a2 = dotAB(m2, cv, pv, a2);                                    \
                a3 = dotAB(m3, cv, pv, a3);                                    \
            }                                                                  \
        }                                                                      \
        _Pragma("unroll")                                                      \
        for (int off = 16; off; off >>= 1) {                                   \
            a0 += __shfl_xor_sync(0xffffffffu, a0, off);                       \
            a1 += __shfl_xor_sync(0xffffffffu, a1, off);                       \
            a2 += __shfl_xor_sync(0xffffffffu, a2, off);                       \
            a3 += __shfl_xor_sync(0xffffffffu, a3, off);                       \
        }                                                                      \
        if (lane == 0) {                                                       \
            s_part[(rg * 4 + 0) * 4 + ks] = a0;                                \
            s_part[(rg * 4 + 1) * 4 + ks] = a1;                                \
            s_part[(rg * 4 + 2) * 4 + ks] = a2;                                \
            s_part[(rg * 4 + 3) * 4 + ks] = a3;                                \
        }                                                                      \
        __syncthreads();                                                       \
        if (tid < ROWS_PER_CTA) {                                              \
            float v = (s_part[tid * 4 + 0] + s_part[tid * 4 + 1]) +            \
                      (s_part[tid * 4 + 2] + s_part[tid * 4 + 3]);             \
            __stcg(out + (size_t)(T) * D + row_base + tid, v);                 \
        }                                                                      \
        __syncthreads();                                                       \
        if (tid == 0) {                                                        \
            __threadfence();                                                   \
            atomicAdd(&g_bar, 1u);                                             \
            unsigned int target = (unsigned int)((T) + 1) * NCTA;              \
            while (*(volatile unsigned int*)&g_bar < target) { }               \
            __threadfence();                                                   \
        }                                                                      \
        __syncthreads();                                                       \
    }

    for (int tb = 0; tb < NSTEPS; tb += 2) {
        RNN_STEP(tb,     s_v0, s_v1);   // even step: cur=v0, prev=v1
        RNN_STEP(tb + 1, s_v1, s_v0);   // odd  step: cur=v1, prev=v0
    }
#undef RNN_STEP
}

// ---------------------------------------------------------------------------
// Launch: prep (convert + barrier reset), then ONE persistent kernel.
// 98,560 B dynamic SMEM per CTA -> 2 CTAs/SM; 256 CTAs all co-resident.
// ---------------------------------------------------------------------------
extern "C" void kernel_launch(void* const* d_in, const int* in_sizes, int n_in,
                              void* d_out, int out_size) {
    const float* init = (const float*)d_in[0];  // [2, D]
    const float* A    = (const float*)d_in[1];  // [D, D]
    const float* B    = (const float*)d_in[2];  // [D, D]
    float* out = (float*)d_out;                 // [NSTEPS, D]

    const int smem_bytes = 33024 + 4 * 1024 * 16;  // 98,560 B
    cudaFuncSetAttribute(rnn_kernel, cudaFuncAttributeMaxDynamicSharedMemorySize,
                         smem_bytes);

    prep_kernel<<<(D * (size_t)D / 4) / 256, 256>>>(A, B);
    rnn_kernel<<<NCTA, NTHREADS, smem_bytes>>>(init, out);
}